// round 11
// baseline (speedup 1.0000x reference)
#include <cuda_runtime.h>
#include <cuda_bf16.h>
#include <cstdint>
#include <math.h>

// Problem constants
#define BATCH 2
#define HIMG 256
#define WIMG 256
#define NTOK (HIMG*WIMG)
#define CDIM 64
#define HS 128
#define WS 128
#define NS (HS*WS)
#define LH 33
#define LWIN 33
#define NWIN (LH*LWIN)
#define SCALE 0.125f
#define EPSLN 1e-5f
#define PLANE ((size_t)BATCH*NTOK*CDIM)

typedef unsigned long long u64;
typedef unsigned int u32;

// ---------------- packed f32x2 helpers (CUDA-core kernels) -----------------
__device__ __forceinline__ u64 pack2(float lo, float hi) {
    u64 r; asm("mov.b64 %0,{%1,%2};" : "=l"(r) : "f"(lo), "f"(hi)); return r;
}
__device__ __forceinline__ u64 ffma2(u64 a, u64 b, u64 c) {
    u64 d; asm("fma.rn.f32x2 %0,%1,%2,%3;" : "=l"(d) : "l"(a), "l"(b), "l"(c)); return d;
}
__device__ __forceinline__ u64 add2(u64 a, u64 b) {
    u64 d; asm("add.rn.f32x2 %0,%1,%2;" : "=l"(d) : "l"(a), "l"(b)); return d;
}
__device__ __forceinline__ float2 unpack2(u64 a) {
    float2 f; asm("mov.b64 {%0,%1},%2;" : "=f"(f.x), "=f"(f.y) : "l"(a)); return f;
}
__device__ __forceinline__ float hsum2(u64 a) { float2 f = unpack2(a); return f.x + f.y; }

// ---------------- mma.sync / ldmatrix helpers (sm_80+, in compute_100) -----
__device__ __forceinline__ uint32_t smem_u32(const void* p) {
    uint32_t a;
    asm("{ .reg .u64 tmp; cvta.to.shared.u64 tmp, %1; cvt.u32.u64 %0, tmp; }"
        : "=r"(a) : "l"(p));
    return a;
}
__device__ __forceinline__ void ldsm_x4(u32* r, u32 addr) {
    asm volatile("ldmatrix.sync.aligned.m8n8.x4.shared.b16 {%0,%1,%2,%3}, [%4];"
        : "=r"(r[0]), "=r"(r[1]), "=r"(r[2]), "=r"(r[3]) : "r"(addr));
}
__device__ __forceinline__ void ldsm_x2(u32* r, u32 addr) {
    asm volatile("ldmatrix.sync.aligned.m8n8.x2.shared.b16 {%0,%1}, [%2];"
        : "=r"(r[0]), "=r"(r[1]) : "r"(addr));
}
__device__ __forceinline__ void ldsm_x2t(u32* r, u32 addr) {
    asm volatile("ldmatrix.sync.aligned.m8n8.x2.trans.shared.b16 {%0,%1}, [%2];"
        : "=r"(r[0]), "=r"(r[1]) : "r"(addr));
}
__device__ __forceinline__ void mma_bf16(float* c, const u32* a, const u32* b) {
    asm volatile("mma.sync.aligned.m16n8k16.row.col.f32.bf16.bf16.f32 "
        "{%0,%1,%2,%3}, {%4,%5,%6,%7}, {%8,%9}, {%0,%1,%2,%3};"
        : "+f"(c[0]), "+f"(c[1]), "+f"(c[2]), "+f"(c[3])
        : "r"(a[0]), "r"(a[1]), "r"(a[2]), "r"(a[3]), "r"(b[0]), "r"(b[1]));
}

// pack (lo,hi) floats into bf16x2 (lo at [15:0])
__device__ __forceinline__ u32 bf2(float lo, float hi) {
    u32 r; asm("cvt.rn.satfinite.bf16x2.f32 %0, %1, %2;" : "=r"(r) : "f"(hi), "f"(lo));
    return r;
}
// split pair (f0,f1) -> hi bf16x2 and residual-lo bf16x2
__device__ __forceinline__ void split2(float f0, float f1, u32& h, u32& l) {
    h = bf2(f0, f1);
    float f0h = __uint_as_float(h << 16);
    float f1h = __uint_as_float(h & 0xFFFF0000u);
    l = bf2(f0 - f0h, f1 - f1h);
}

// Scratch
__device__ float d_q  [BATCH*NTOK*CDIM];
__device__ float d_k  [BATCH*NS*CDIM];
__device__ float d_v  [BATCH*NS*CDIM];
// 4 parity planes: window (wy,wx) writes plane (wy&1)*2+(wx&1).
// Every in-image (plane,pixel) slot is written exactly once -> no zeroing, no atomics.
__device__ float d_acc4[4*PLANE];

// ---------------------------------------------------------------------------
// Kernel 1: q = x @ q_w^T — 1 row/thread, 2 CTAs/SM (streaming, occupancy-first)
// ---------------------------------------------------------------------------
__global__ __launch_bounds__(256, 2) void qproj_kernel(
    const float* __restrict__ x, const float* __restrict__ qw)
{
    __shared__ float W[64*64];
    int t = threadIdx.x;
    for (int i = t; i < 4096; i += 256) W[i] = qw[i];
    __syncthreads();

    size_t row = (size_t)blockIdx.x * 256 + t;
    const ulonglong2* xr = (const ulonglong2*)(x + row * 64);
    ulonglong2 xv[16];
    #pragma unroll
    for (int i = 0; i < 16; i++) xv[i] = xr[i];

    float* qo = d_q + row * 64;
    #pragma unroll 4
    for (int d = 0; d < 64; d++) {
        const ulonglong2* wr = (const ulonglong2*)(W + d*64);
        u64 s2 = 0ull;
        #pragma unroll
        for (int i = 0; i < 16; i++) {
            ulonglong2 w = wr[i];
            s2 = ffma2(xv[i].x, w.x, s2);
            s2 = ffma2(xv[i].y, w.y, s2);
        }
        qo[d] = hsum2(s2);
    }
}

// ---------------------------------------------------------------------------
// Kernel 2: 2x2/s2 conv + bias -> LayerNorm -> k,v
// 128 threads/block, 256 blocks (all SMs occupied).
// ---------------------------------------------------------------------------
__global__ __launch_bounds__(128) void conv_ln_kv_kernel(
    const float* __restrict__ x,  const float* __restrict__ sr_w,
    const float* __restrict__ sr_b, const float* __restrict__ ln_w,
    const float* __restrict__ ln_b, const float* __restrict__ kv_w)
{
    extern __shared__ float sm[];
    float* Wc  = sm;
    float* KVW = sm + 16384;
    float* LNW = KVW + 8192;
    float* LNB = LNW + 64;
    float* SRB = LNB + 64;
    int t = threadIdx.x;

    for (int i = t; i < 16384; i += 128) {
        int c  = i >> 8;
        int ci = (i >> 2) & 63;
        int p  = i & 3;
        Wc[(p*64 + c)*64 + ci] = sr_w[i];
    }
    for (int i = t; i < 8192; i += 128) KVW[i] = kv_w[i];
    if (t < 64) { LNW[t] = ln_w[t]; LNB[t] = ln_b[t]; }
    else if (t < 128) { SRB[t-64] = sr_b[t-64]; }
    __syncthreads();

    int idx = blockIdx.x * 128 + t;
    int b  = idx >> 14;
    int hs = (idx >> 7) & 127;
    int ws = idx & 127;

    float acc[64];
    #pragma unroll
    for (int c = 0; c < 64; c++) acc[c] = SRB[c];

    for (int p = 0; p < 4; p++) {
        int h = hs*2 + (p >> 1), w = ws*2 + (p & 1);
        const ulonglong2* xin = (const ulonglong2*)(x + ((size_t)b*NTOK + h*WIMG + w)*64);
        ulonglong2 in[16];
        #pragma unroll
        for (int i = 0; i < 16; i++) in[i] = xin[i];
        #pragma unroll 4
        for (int c = 0; c < 64; c++) {
            const ulonglong2* wr = (const ulonglong2*)(Wc + (p*64 + c)*64);
            u64 s2 = 0ull;
            #pragma unroll
            for (int i = 0; i < 16; i++) {
                ulonglong2 w4 = wr[i];
                s2 = ffma2(in[i].x, w4.x, s2);
                s2 = ffma2(in[i].y, w4.y, s2);
            }
            acc[c] += hsum2(s2);
        }
    }

    float mu = 0.f, sq = 0.f;
    #pragma unroll
    for (int c = 0; c < 64; c++) { mu += acc[c]; sq += acc[c]*acc[c]; }
    mu *= (1.f/64.f);
    float var = sq * (1.f/64.f) - mu*mu;
    float rstd = rsqrtf(var + EPSLN);
    #pragma unroll
    for (int c = 0; c < 64; c++) acc[c] = (acc[c] - mu) * rstd * LNW[c] + LNB[c];

    u64 a2[32];
    #pragma unroll
    for (int i = 0; i < 32; i++) a2[i] = pack2(acc[2*i], acc[2*i+1]);

    float* kout = d_k + (size_t)idx * 64;
    float* vout = d_v + (size_t)idx * 64;
    #pragma unroll 4
    for (int d = 0; d < 64; d++) {
        const ulonglong2* wr = (const ulonglong2*)(KVW + d*64);
        u64 s2 = 0ull;
        #pragma unroll
        for (int i = 0; i < 16; i++) {
            ulonglong2 w4 = wr[i];
            s2 = ffma2(a2[2*i], w4.x, s2);
            s2 = ffma2(a2[2*i+1], w4.y, s2);
        }
        kout[d] = hsum2(s2);
    }
    #pragma unroll 4
    for (int d = 0; d < 64; d++) {
        const ulonglong2* wr = (const ulonglong2*)(KVW + (64+d)*64);
        u64 s2 = 0ull;
        #pragma unroll
        for (int i = 0; i < 16; i++) {
            ulonglong2 w4 = wr[i];
            s2 = ffma2(a2[2*i], w4.x, s2);
            s2 = ffma2(a2[2*i+1], w4.y, s2);
        }
        vout[d] = hsum2(s2);
    }
}

// ---------------------------------------------------------------------------
// Kernel 3: mma.sync attention. One window/block, 256 threads (8 warps),
// each warp owns 2 m-tiles (32 q-rows). bf16x3 split (hh+hl+lh).
// Output written with PLAIN STG.64 into the window's parity plane
// (no atomics, no zeroing needed).
// ---------------------------------------------------------------------------
#define QS 144
#define O_QHI 0
#define O_QLO 36864
#define O_KHI 73728
#define O_KLO 82944
#define O_VHI 92160
#define O_VLO 101376
#define SM_ATTN 110592

__global__ __launch_bounds__(256) void attn_kernel(
    const float* __restrict__ pos_q, const float* __restrict__ pos_k)
{
    extern __shared__ char smc[];
    uint32_t sb = smem_u32(smc);
    int t = threadIdx.x;
    int lane = t & 31;
    int wid  = t >> 5;          // 0..7
    int win = blockIdx.x, b = blockIdx.y;
    int wy = win / LWIN, wx = win % LWIN;
    int pl = ((wy & 1) << 1) | (wx & 1);
    float* plane = d_acc4 + (size_t)pl * PLANE;

    // ---- stage roped K (hi/lo) and V (hi/lo, row-major [k][d]) ----
    {
        int r  = t >> 2;            // k-row 0..63
        int qt = t & 3;             // 16-channel quarter
        int kyy = r >> 3, kxx = r & 7;
        int hs = wy*4 - 4 + kyy, ws = wx*4 - 4 + kxx;
        bool ok = (hs >= 0 && hs < HS && ws >= 0 && ws < WS);
        size_t gro = ((size_t)b*NS + hs*WS + ws)*64 + qt*16;
        const float4* krow = (const float4*)(d_k + gro);
        const float4* vrow = (const float4*)(d_v + gro);
        const float4* prow = (const float4*)(pos_k + r*64 + qt*16);
        #pragma unroll
        for (int i = 0; i < 4; i++) {
            int c = qt*16 + i*4;
            float4 kk = ok ? krow[i] : make_float4(0.f,0.f,0.f,0.f);
            float4 p4 = prow[i];
            float e0 = p4.y*kk.y - p4.x*kk.x;
            float e1 = p4.y*kk.y + p4.x*kk.x;
            float e2 = p4.w*kk.w - p4.z*kk.z;
            float e3 = p4.w*kk.w + p4.z*kk.z;
            u32 h01, l01, h23, l23;
            split2(e0, e1, h01, l01);
            split2(e2, e3, h23, l23);
            u32 off = (u32)(r*QS + c*2);
            *(u64*)(smc + O_KHI + off) = ((u64)h23 << 32) | h01;
            *(u64*)(smc + O_KLO + off) = ((u64)l23 << 32) | l01;
            float4 vv = ok ? vrow[i] : make_float4(0.f,0.f,0.f,0.f);
            u32 vh01, vl01, vh23, vl23;
            split2(vv.x, vv.y, vh01, vl01);
            split2(vv.z, vv.w, vh23, vl23);
            *(u64*)(smc + O_VHI + off) = ((u64)vh23 << 32) | vh01;
            *(u64*)(smc + O_VLO + off) = ((u64)vl23 << 32) | vl01;
        }
    }

    // ---- stage roped+scaled Q row t (hi/lo) ----
    {
        int m = t;
        int ky = m >> 4, kx = m & 15;
        int h = wy*8 - 8 + ky, w = wx*8 - 8 + kx;
        bool valid = (h >= 0 && h < HIMG && w >= 0 && w < WIMG);
        const float4* qr = (const float4*)(d_q + ((size_t)b*NTOK + h*WIMG + w)*64);
        const float4* pr = (const float4*)(pos_q + m*64);
        #pragma unroll
        for (int i = 0; i < 16; i++) {
            float4 qq = valid ? qr[i] : make_float4(0.f,0.f,0.f,0.f);
            float4 p4 = pr[i];
            float e0 = (p4.y*qq.y - p4.x*qq.x) * SCALE;
            float e1 = (p4.y*qq.y + p4.x*qq.x) * SCALE;
            float e2 = (p4.w*qq.w - p4.z*qq.z) * SCALE;
            float e3 = (p4.w*qq.w + p4.z*qq.z) * SCALE;
            u32 h01, l01, h23, l23;
            split2(e0, e1, h01, l01);
            split2(e2, e3, h23, l23);
            u32 off = (u32)(m*QS + i*8);
            *(u64*)(smc + O_QHI + off) = ((u64)h23 << 32) | h01;
            *(u64*)(smc + O_QLO + off) = ((u64)l23 << 32) | l01;
        }
    }
    __syncthreads();

    int lr = lane & 7, quad = lane >> 3;
    int li = lane & 15;
    int wb = wid * 32;          // 32 q-rows per warp
    u32 qh = sb + O_QHI, ql = sb + O_QLO;
    u32 kh = sb + O_KHI, kl = sb + O_KLO;
    u32 vh = sb + O_VHI, vl = sb + O_VLO;

    // ---- S = Q K^T : C fragments cs[m-tile][n-tile][4] ----
    float cs[2][8][4];
    #pragma unroll
    for (int i = 0; i < 2; i++)
        #pragma unroll
        for (int j = 0; j < 8; j++)
            #pragma unroll
            for (int v = 0; v < 4; v++) cs[i][j][v] = 0.f;

    #pragma unroll
    for (int s = 0; s < 4; s++) {
        int d0 = 16*s;
        u32 ah[2][4], al[2][4];
        #pragma unroll
        for (int i = 0; i < 2; i++) {
            u32 off = (u32)((wb + 16*i + lr + ((quad & 1) << 3)) * QS
                          + (d0 + ((quad & 2) << 2)) * 2);
            ldsm_x4(ah[i], qh + off);
            ldsm_x4(al[i], ql + off);
        }
        #pragma unroll
        for (int j = 0; j < 8; j++) {
            u32 off = (u32)((8*j + (li & 7)) * QS + (d0 + ((li >> 3) << 3)) * 2);
            u32 bh[2], bl[2];
            ldsm_x2(bh, kh + off);
            ldsm_x2(bl, kl + off);
            #pragma unroll
            for (int i = 0; i < 2; i++) {
                mma_bf16(cs[i][j], ah[i], bh);
                mma_bf16(cs[i][j], ah[i], bl);
                mma_bf16(cs[i][j], al[i], bh);
            }
        }
    }

    // ---- softmax per row (quad shfl reduce), store P into Q smem ----
    #pragma unroll
    for (int i = 0; i < 2; i++) {
        float mx0 = -1e30f, mx1 = -1e30f;
        #pragma unroll
        for (int j = 0; j < 8; j++) {
            mx0 = fmaxf(mx0, fmaxf(cs[i][j][0], cs[i][j][1]));
            mx1 = fmaxf(mx1, fmaxf(cs[i][j][2], cs[i][j][3]));
        }
        mx0 = fmaxf(mx0, __shfl_xor_sync(0xffffffffu, mx0, 1));
        mx0 = fmaxf(mx0, __shfl_xor_sync(0xffffffffu, mx0, 2));
        mx1 = fmaxf(mx1, __shfl_xor_sync(0xffffffffu, mx1, 1));
        mx1 = fmaxf(mx1, __shfl_xor_sync(0xffffffffu, mx1, 2));
        float sm0 = 0.f, sm1 = 0.f;
        #pragma unroll
        for (int j = 0; j < 8; j++) {
            cs[i][j][0] = __expf(cs[i][j][0] - mx0);
            cs[i][j][1] = __expf(cs[i][j][1] - mx0);
            cs[i][j][2] = __expf(cs[i][j][2] - mx1);
            cs[i][j][3] = __expf(cs[i][j][3] - mx1);
            sm0 += cs[i][j][0] + cs[i][j][1];
            sm1 += cs[i][j][2] + cs[i][j][3];
        }
        sm0 += __shfl_xor_sync(0xffffffffu, sm0, 1);
        sm0 += __shfl_xor_sync(0xffffffffu, sm0, 2);
        sm1 += __shfl_xor_sync(0xffffffffu, sm1, 1);
        sm1 += __shfl_xor_sync(0xffffffffu, sm1, 2);
        float inv0 = 1.f / sm0, inv1 = 1.f / sm1;

        int r0 = wb + 16*i + (lane >> 2);
        int cb = 2*(lane & 3);
        #pragma unroll
        for (int j = 0; j < 8; j++) {
            u32 h, l;
            split2(cs[i][j][0]*inv0, cs[i][j][1]*inv0, h, l);
            u32 off = (u32)(r0*QS + (8*j + cb)*2);
            *(u32*)(smc + O_QHI + off) = h;
            *(u32*)(smc + O_QLO + off) = l;
            split2(cs[i][j][2]*inv1, cs[i][j][3]*inv1, h, l);
            off = (u32)((r0 + 8)*QS + (8*j + cb)*2);
            *(u32*)(smc + O_QHI + off) = h;
            *(u32*)(smc + O_QLO + off) = l;
        }
    }
    __syncwarp();

    // ---- O = P V : per m-tile, accumulate; plain stores into parity plane ----
    #pragma unroll
    for (int i = 0; i < 2; i++) {
        u32 ph[4][4], pll[4][4];
        #pragma unroll
        for (int s = 0; s < 4; s++) {
            u32 off = (u32)((wb + 16*i + lr + ((quad & 1) << 3)) * QS
                          + (16*s + ((quad & 2) << 2)) * 2);
            ldsm_x4(ph[s], qh + off);
            ldsm_x4(pll[s], ql + off);
        }
        int r0 = wb + 16*i + (lane >> 2);
        int ky = r0 >> 4;
        int kx0 = r0 & 15;
        int h = wy*8 - 8 + ky;
        int w0 = wx*8 - 8 + kx0;
        int w1 = w0 + 8;
        bool hok = (h >= 0 && h < HIMG);
        bool ok0 = hok && (w0 >= 0) && (w0 < WIMG);
        bool ok1 = hok && (w1 < WIMG);
        #pragma unroll
        for (int j = 0; j < 8; j++) {
            float o[4] = {0.f, 0.f, 0.f, 0.f};
            #pragma unroll
            for (int s = 0; s < 4; s++) {
                u32 off = (u32)((16*s + li) * QS + (8*j) * 2);
                u32 bh[2], bl[2];
                ldsm_x2t(bh, vh + off);
                ldsm_x2t(bl, vl + off);
                mma_bf16(o, ph[s], bh);
                mma_bf16(o, ph[s], bl);
                mma_bf16(o, pll[s], bh);
            }
            int d0 = 8*j + 2*(lane & 3);
            if (ok0) {
                *(float2*)(plane + ((size_t)b*NTOK + h*WIMG + w0)*64 + d0)
                    = make_float2(o[0], o[1]);
            }
            if (ok1) {
                *(float2*)(plane + ((size_t)b*NTOK + h*WIMG + w1)*64 + d0)
                    = make_float2(o[2], o[3]);
            }
        }
    }
}

// ---------------------------------------------------------------------------
// Kernel 4: fold (sum 4 parity planes) + out projection — 1 row/thread,
// 2 CTAs/SM (streaming, occupancy-first). Plane sum fused into load stream.
// ---------------------------------------------------------------------------
__global__ __launch_bounds__(256, 2) void proj_kernel(
    const float* __restrict__ pw, const float* __restrict__ pb,
    float* __restrict__ out)
{
    __shared__ float PW[4096];
    __shared__ float PB[64];
    int t = threadIdx.x;
    for (int i = t; i < 4096; i += 256) PW[i] = pw[i];
    if (t < 64) PB[t] = pb[t];
    __syncthreads();

    size_t r = (size_t)blockIdx.x * 256 + t;

    ulonglong2 a[16];
    {
        const ulonglong2* p0 = (const ulonglong2*)(d_acc4 + r * 64);
        #pragma unroll
        for (int i = 0; i < 16; i++) a[i] = p0[i];
        #pragma unroll
        for (int p = 1; p < 4; p++) {
            const ulonglong2* q = (const ulonglong2*)(d_acc4 + p*PLANE + r * 64);
            #pragma unroll
            for (int i = 0; i < 16; i++) {
                ulonglong2 v = q[i];
                a[i].x = add2(a[i].x, v.x);
                a[i].y = add2(a[i].y, v.y);
            }
        }
    }

    float* od = out + r * 64;
    #pragma unroll 4
    for (int d = 0; d < 64; d++) {
        const ulonglong2* wr = (const ulonglong2*)(PW + d*64);
        u64 s2 = 0ull;
        #pragma unroll
        for (int i = 0; i < 16; i++) {
            ulonglong2 w = wr[i];
            s2 = ffma2(a[i].x, w.x, s2);
            s2 = ffma2(a[i].y, w.y, s2);
        }
        od[d] = hsum2(s2) + PB[d];
    }
}

// ---------------------------------------------------------------------------
extern "C" void kernel_launch(void* const* d_in, const int* in_sizes, int n_in,
                              void* d_out, int out_size)
{
    const float* x       = (const float*)d_in[0];
    const float* pos_q   = (const float*)d_in[1];
    const float* pos_ksr = (const float*)d_in[2];
    const float* q_w     = (const float*)d_in[3];
    const float* kv_w    = (const float*)d_in[4];
    const float* sr_w    = (const float*)d_in[5];
    const float* sr_b    = (const float*)d_in[6];
    const float* ln_w    = (const float*)d_in[7];
    const float* ln_b    = (const float*)d_in[8];
    const float* proj_w  = (const float*)d_in[9];
    const float* proj_b  = (const float*)d_in[10];
    float* out = (float*)d_out;

    const int smem_conv = (16384 + 8192 + 192) * 4;
    cudaFuncSetAttribute(conv_ln_kv_kernel,
        cudaFuncAttributeMaxDynamicSharedMemorySize, smem_conv);
    cudaFuncSetAttribute(attn_kernel,
        cudaFuncAttributeMaxDynamicSharedMemorySize, SM_ATTN);

    qproj_kernel<<<(BATCH*NTOK)/256, 256>>>(x, q_w);
    conv_ln_kv_kernel<<<(BATCH*NS)/128, 128, smem_conv>>>(
        x, sr_w, sr_b, ln_w, ln_b, kv_w);
    attn_kernel<<<dim3(NWIN, BATCH), 256, SM_ATTN>>>(pos_q, pos_ksr);
    proj_kernel<<<(BATCH*NTOK)/256, 256>>>(proj_w, proj_b, out);
}

// round 12
// speedup vs baseline: 1.0414x; 1.0414x over previous
#include <cuda_runtime.h>
#include <cuda_bf16.h>
#include <cstdint>
#include <math.h>

// Problem constants
#define BATCH 2
#define HIMG 256
#define WIMG 256
#define NTOK (HIMG*WIMG)
#define CDIM 64
#define HS 128
#define WS 128
#define NS (HS*WS)
#define LH 33
#define LWIN 33
#define NWIN (LH*LWIN)
#define SCALE 0.125f
#define EPSLN 1e-5f

typedef unsigned long long u64;
typedef unsigned int u32;

// ---------------- packed f32x2 helpers (CUDA-core kernels) -----------------
__device__ __forceinline__ u64 pack2(float lo, float hi) {
    u64 r; asm("mov.b64 %0,{%1,%2};" : "=l"(r) : "f"(lo), "f"(hi)); return r;
}
__device__ __forceinline__ u64 ffma2(u64 a, u64 b, u64 c) {
    u64 d; asm("fma.rn.f32x2 %0,%1,%2,%3;" : "=l"(d) : "l"(a), "l"(b), "l"(c)); return d;
}
__device__ __forceinline__ float2 unpack2(u64 a) {
    float2 f; asm("mov.b64 {%0,%1},%2;" : "=f"(f.x), "=f"(f.y) : "l"(a)); return f;
}
__device__ __forceinline__ float hsum2(u64 a) { float2 f = unpack2(a); return f.x + f.y; }

// ---------------- mma.sync / ldmatrix helpers (sm_80+, in compute_100) -----
__device__ __forceinline__ uint32_t smem_u32(const void* p) {
    uint32_t a;
    asm("{ .reg .u64 tmp; cvta.to.shared.u64 tmp, %1; cvt.u32.u64 %0, tmp; }"
        : "=r"(a) : "l"(p));
    return a;
}
__device__ __forceinline__ void ldsm_x4(u32* r, u32 addr) {
    asm volatile("ldmatrix.sync.aligned.m8n8.x4.shared.b16 {%0,%1,%2,%3}, [%4];"
        : "=r"(r[0]), "=r"(r[1]), "=r"(r[2]), "=r"(r[3]) : "r"(addr));
}
__device__ __forceinline__ void ldsm_x2(u32* r, u32 addr) {
    asm volatile("ldmatrix.sync.aligned.m8n8.x2.shared.b16 {%0,%1}, [%2];"
        : "=r"(r[0]), "=r"(r[1]) : "r"(addr));
}
__device__ __forceinline__ void ldsm_x2t(u32* r, u32 addr) {
    asm volatile("ldmatrix.sync.aligned.m8n8.x2.trans.shared.b16 {%0,%1}, [%2];"
        : "=r"(r[0]), "=r"(r[1]) : "r"(addr));
}
__device__ __forceinline__ void mma_bf16(float* c, const u32* a, const u32* b) {
    asm volatile("mma.sync.aligned.m16n8k16.row.col.f32.bf16.bf16.f32 "
        "{%0,%1,%2,%3}, {%4,%5,%6,%7}, {%8,%9}, {%0,%1,%2,%3};"
        : "+f"(c[0]), "+f"(c[1]), "+f"(c[2]), "+f"(c[3])
        : "r"(a[0]), "r"(a[1]), "r"(a[2]), "r"(a[3]), "r"(b[0]), "r"(b[1]));
}

// pack (lo,hi) floats into bf16x2 (lo at [15:0])
__device__ __forceinline__ u32 bf2(float lo, float hi) {
    u32 r; asm("cvt.rn.satfinite.bf16x2.f32 %0, %1, %2;" : "=r"(r) : "f"(hi), "f"(lo));
    return r;
}
// split pair (f0,f1) -> hi bf16x2 and residual-lo bf16x2
__device__ __forceinline__ void split2(float f0, float f1, u32& h, u32& l) {
    h = bf2(f0, f1);
    float f0h = __uint_as_float(h << 16);
    float f1h = __uint_as_float(h & 0xFFFF0000u);
    l = bf2(f0 - f0h, f1 - f1h);
}

// Scratch — total working set (q + k + v + acc ≈ 84 MB) fits in L2 (~126 MB)
__device__ float d_q  [BATCH*NTOK*CDIM];
__device__ float d_k  [BATCH*NS*CDIM];
__device__ float d_v  [BATCH*NS*CDIM];
__device__ float d_acc[BATCH*NTOK*CDIM];   // 33.5 MB fold accumulator (L2-resident)

// ---------------------------------------------------------------------------
// Kernel 0: zero the fold accumulator
// ---------------------------------------------------------------------------
__global__ __launch_bounds__(256) void zero_kernel()
{
    size_t i = (size_t)blockIdx.x * 256 + threadIdx.x;
    ((float4*)d_acc)[i] = make_float4(0.f, 0.f, 0.f, 0.f);
}

// ---------------------------------------------------------------------------
// Kernel 1: q = x @ q_w^T — 1 row/thread, 2 CTAs/SM (streaming, occupancy-first)
// ---------------------------------------------------------------------------
__global__ __launch_bounds__(256, 2) void qproj_kernel(
    const float* __restrict__ x, const float* __restrict__ qw)
{
    __shared__ float W[64*64];
    int t = threadIdx.x;
    for (int i = t; i < 4096; i += 256) W[i] = qw[i];
    __syncthreads();

    size_t row = (size_t)blockIdx.x * 256 + t;
    const ulonglong2* xr = (const ulonglong2*)(x + row * 64);
    ulonglong2 xv[16];
    #pragma unroll
    for (int i = 0; i < 16; i++) xv[i] = xr[i];

    float* qo = d_q + row * 64;
    #pragma unroll 4
    for (int d = 0; d < 64; d++) {
        const ulonglong2* wr = (const ulonglong2*)(W + d*64);
        u64 s2 = 0ull;
        #pragma unroll
        for (int i = 0; i < 16; i++) {
            ulonglong2 w = wr[i];
            s2 = ffma2(xv[i].x, w.x, s2);
            s2 = ffma2(xv[i].y, w.y, s2);
        }
        qo[d] = hsum2(s2);
    }
}

// ---------------------------------------------------------------------------
// Kernel 2: 2x2/s2 conv + bias -> LayerNorm -> k,v
// 128 threads/block, 256 blocks (all SMs occupied).
// ---------------------------------------------------------------------------
__global__ __launch_bounds__(128) void conv_ln_kv_kernel(
    const float* __restrict__ x,  const float* __restrict__ sr_w,
    const float* __restrict__ sr_b, const float* __restrict__ ln_w,
    const float* __restrict__ ln_b, const float* __restrict__ kv_w)
{
    extern __shared__ float sm[];
    float* Wc  = sm;
    float* KVW = sm + 16384;
    float* LNW = KVW + 8192;
    float* LNB = LNW + 64;
    float* SRB = LNB + 64;
    int t = threadIdx.x;

    for (int i = t; i < 16384; i += 128) {
        int c  = i >> 8;
        int ci = (i >> 2) & 63;
        int p  = i & 3;
        Wc[(p*64 + c)*64 + ci] = sr_w[i];
    }
    for (int i = t; i < 8192; i += 128) KVW[i] = kv_w[i];
    if (t < 64) { LNW[t] = ln_w[t]; LNB[t] = ln_b[t]; }
    else if (t < 128) { SRB[t-64] = sr_b[t-64]; }
    __syncthreads();

    int idx = blockIdx.x * 128 + t;
    int b  = idx >> 14;
    int hs = (idx >> 7) & 127;
    int ws = idx & 127;

    float acc[64];
    #pragma unroll
    for (int c = 0; c < 64; c++) acc[c] = SRB[c];

    for (int p = 0; p < 4; p++) {
        int h = hs*2 + (p >> 1), w = ws*2 + (p & 1);
        const ulonglong2* xin = (const ulonglong2*)(x + ((size_t)b*NTOK + h*WIMG + w)*64);
        ulonglong2 in[16];
        #pragma unroll
        for (int i = 0; i < 16; i++) in[i] = xin[i];
        #pragma unroll 4
        for (int c = 0; c < 64; c++) {
            const ulonglong2* wr = (const ulonglong2*)(Wc + (p*64 + c)*64);
            u64 s2 = 0ull;
            #pragma unroll
            for (int i = 0; i < 16; i++) {
                ulonglong2 w4 = wr[i];
                s2 = ffma2(in[i].x, w4.x, s2);
                s2 = ffma2(in[i].y, w4.y, s2);
            }
            acc[c] += hsum2(s2);
        }
    }

    float mu = 0.f, sq = 0.f;
    #pragma unroll
    for (int c = 0; c < 64; c++) { mu += acc[c]; sq += acc[c]*acc[c]; }
    mu *= (1.f/64.f);
    float var = sq * (1.f/64.f) - mu*mu;
    float rstd = rsqrtf(var + EPSLN);
    #pragma unroll
    for (int c = 0; c < 64; c++) acc[c] = (acc[c] - mu) * rstd * LNW[c] + LNB[c];

    u64 a2[32];
    #pragma unroll
    for (int i = 0; i < 32; i++) a2[i] = pack2(acc[2*i], acc[2*i+1]);

    float* kout = d_k + (size_t)idx * 64;
    float* vout = d_v + (size_t)idx * 64;
    #pragma unroll 4
    for (int d = 0; d < 64; d++) {
        const ulonglong2* wr = (const ulonglong2*)(KVW + d*64);
        u64 s2 = 0ull;
        #pragma unroll
        for (int i = 0; i < 16; i++) {
            ulonglong2 w4 = wr[i];
            s2 = ffma2(a2[2*i], w4.x, s2);
            s2 = ffma2(a2[2*i+1], w4.y, s2);
        }
        kout[d] = hsum2(s2);
    }
    #pragma unroll 4
    for (int d = 0; d < 64; d++) {
        const ulonglong2* wr = (const ulonglong2*)(KVW + (64+d)*64);
        u64 s2 = 0ull;
        #pragma unroll
        for (int i = 0; i < 16; i++) {
            ulonglong2 w4 = wr[i];
            s2 = ffma2(a2[2*i], w4.x, s2);
            s2 = ffma2(a2[2*i+1], w4.y, s2);
        }
        vout[d] = hsum2(s2);
    }
}

// ---------------------------------------------------------------------------
// Kernel 3: mma.sync attention. One window/block, 256 threads (8 warps),
// each warp owns 2 m-tiles (32 q-rows). bf16x3 split (hh+hl+lh).
// Fold via red.global.add.v2 into L2-resident d_acc (R9 configuration).
// ---------------------------------------------------------------------------
#define QS 144
#define O_QHI 0
#define O_QLO 36864
#define O_KHI 73728
#define O_KLO 82944
#define O_VHI 92160
#define O_VLO 101376
#define SM_ATTN 110592

__global__ __launch_bounds__(256) void attn_kernel(
    const float* __restrict__ pos_q, const float* __restrict__ pos_k)
{
    extern __shared__ char smc[];
    uint32_t sb = smem_u32(smc);
    int t = threadIdx.x;
    int lane = t & 31;
    int wid  = t >> 5;          // 0..7
    int win = blockIdx.x, b = blockIdx.y;
    int wy = win / LWIN, wx = win % LWIN;

    // ---- stage roped K (hi/lo) and V (hi/lo, row-major [k][d]) ----
    {
        int r  = t >> 2;            // k-row 0..63
        int qt = t & 3;             // 16-channel quarter
        int kyy = r >> 3, kxx = r & 7;
        int hs = wy*4 - 4 + kyy, ws = wx*4 - 4 + kxx;
        bool ok = (hs >= 0 && hs < HS && ws >= 0 && ws < WS);
        size_t gro = ((size_t)b*NS + hs*WS + ws)*64 + qt*16;
        const float4* krow = (const float4*)(d_k + gro);
        const float4* vrow = (const float4*)(d_v + gro);
        const float4* prow = (const float4*)(pos_k + r*64 + qt*16);
        #pragma unroll
        for (int i = 0; i < 4; i++) {
            int c = qt*16 + i*4;
            float4 kk = ok ? krow[i] : make_float4(0.f,0.f,0.f,0.f);
            float4 p4 = prow[i];
            float e0 = p4.y*kk.y - p4.x*kk.x;
            float e1 = p4.y*kk.y + p4.x*kk.x;
            float e2 = p4.w*kk.w - p4.z*kk.z;
            float e3 = p4.w*kk.w + p4.z*kk.z;
            u32 h01, l01, h23, l23;
            split2(e0, e1, h01, l01);
            split2(e2, e3, h23, l23);
            u32 off = (u32)(r*QS + c*2);
            *(u64*)(smc + O_KHI + off) = ((u64)h23 << 32) | h01;
            *(u64*)(smc + O_KLO + off) = ((u64)l23 << 32) | l01;
            float4 vv = ok ? vrow[i] : make_float4(0.f,0.f,0.f,0.f);
            u32 vh01, vl01, vh23, vl23;
            split2(vv.x, vv.y, vh01, vl01);
            split2(vv.z, vv.w, vh23, vl23);
            *(u64*)(smc + O_VHI + off) = ((u64)vh23 << 32) | vh01;
            *(u64*)(smc + O_VLO + off) = ((u64)vl23 << 32) | vl01;
        }
    }

    // ---- stage roped+scaled Q row t (hi/lo) ----
    {
        int m = t;
        int ky = m >> 4, kx = m & 15;
        int h = wy*8 - 8 + ky, w = wx*8 - 8 + kx;
        bool valid = (h >= 0 && h < HIMG && w >= 0 && w < WIMG);
        const float4* qr = (const float4*)(d_q + ((size_t)b*NTOK + h*WIMG + w)*64);
        const float4* pr = (const float4*)(pos_q + m*64);
        #pragma unroll
        for (int i = 0; i < 16; i++) {
            float4 qq = valid ? qr[i] : make_float4(0.f,0.f,0.f,0.f);
            float4 p4 = pr[i];
            float e0 = (p4.y*qq.y - p4.x*qq.x) * SCALE;
            float e1 = (p4.y*qq.y + p4.x*qq.x) * SCALE;
            float e2 = (p4.w*qq.w - p4.z*qq.z) * SCALE;
            float e3 = (p4.w*qq.w + p4.z*qq.z) * SCALE;
            u32 h01, l01, h23, l23;
            split2(e0, e1, h01, l01);
            split2(e2, e3, h23, l23);
            u32 off = (u32)(m*QS + i*8);
            *(u64*)(smc + O_QHI + off) = ((u64)h23 << 32) | h01;
            *(u64*)(smc + O_QLO + off) = ((u64)l23 << 32) | l01;
        }
    }
    __syncthreads();

    int lr = lane & 7, quad = lane >> 3;
    int li = lane & 15;
    int wb = wid * 32;          // 32 q-rows per warp
    u32 qh = sb + O_QHI, ql = sb + O_QLO;
    u32 kh = sb + O_KHI, kl = sb + O_KLO;
    u32 vh = sb + O_VHI, vl = sb + O_VLO;

    // ---- S = Q K^T : C fragments cs[m-tile][n-tile][4] ----
    float cs[2][8][4];
    #pragma unroll
    for (int i = 0; i < 2; i++)
        #pragma unroll
        for (int j = 0; j < 8; j++)
            #pragma unroll
            for (int v = 0; v < 4; v++) cs[i][j][v] = 0.f;

    #pragma unroll
    for (int s = 0; s < 4; s++) {
        int d0 = 16*s;
        u32 ah[2][4], al[2][4];
        #pragma unroll
        for (int i = 0; i < 2; i++) {
            u32 off = (u32)((wb + 16*i + lr + ((quad & 1) << 3)) * QS
                          + (d0 + ((quad & 2) << 2)) * 2);
            ldsm_x4(ah[i], qh + off);
            ldsm_x4(al[i], ql + off);
        }
        #pragma unroll
        for (int j = 0; j < 8; j++) {
            u32 off = (u32)((8*j + (li & 7)) * QS + (d0 + ((li >> 3) << 3)) * 2);
            u32 bh[2], bl[2];
            ldsm_x2(bh, kh + off);
            ldsm_x2(bl, kl + off);
            #pragma unroll
            for (int i = 0; i < 2; i++) {
                mma_bf16(cs[i][j], ah[i], bh);
                mma_bf16(cs[i][j], ah[i], bl);
                mma_bf16(cs[i][j], al[i], bh);
            }
        }
    }

    // ---- softmax per row (quad shfl reduce), store P into Q smem ----
    #pragma unroll
    for (int i = 0; i < 2; i++) {
        float mx0 = -1e30f, mx1 = -1e30f;
        #pragma unroll
        for (int j = 0; j < 8; j++) {
            mx0 = fmaxf(mx0, fmaxf(cs[i][j][0], cs[i][j][1]));
            mx1 = fmaxf(mx1, fmaxf(cs[i][j][2], cs[i][j][3]));
        }
        mx0 = fmaxf(mx0, __shfl_xor_sync(0xffffffffu, mx0, 1));
        mx0 = fmaxf(mx0, __shfl_xor_sync(0xffffffffu, mx0, 2));
        mx1 = fmaxf(mx1, __shfl_xor_sync(0xffffffffu, mx1, 1));
        mx1 = fmaxf(mx1, __shfl_xor_sync(0xffffffffu, mx1, 2));
        float sm0 = 0.f, sm1 = 0.f;
        #pragma unroll
        for (int j = 0; j < 8; j++) {
            cs[i][j][0] = __expf(cs[i][j][0] - mx0);
            cs[i][j][1] = __expf(cs[i][j][1] - mx0);
            cs[i][j][2] = __expf(cs[i][j][2] - mx1);
            cs[i][j][3] = __expf(cs[i][j][3] - mx1);
            sm0 += cs[i][j][0] + cs[i][j][1];
            sm1 += cs[i][j][2] + cs[i][j][3];
        }
        sm0 += __shfl_xor_sync(0xffffffffu, sm0, 1);
        sm0 += __shfl_xor_sync(0xffffffffu, sm0, 2);
        sm1 += __shfl_xor_sync(0xffffffffu, sm1, 1);
        sm1 += __shfl_xor_sync(0xffffffffu, sm1, 2);
        float inv0 = 1.f / sm0, inv1 = 1.f / sm1;

        int r0 = wb + 16*i + (lane >> 2);
        int cb = 2*(lane & 3);
        #pragma unroll
        for (int j = 0; j < 8; j++) {
            u32 h, l;
            split2(cs[i][j][0]*inv0, cs[i][j][1]*inv0, h, l);
            u32 off = (u32)(r0*QS + (8*j + cb)*2);
            *(u32*)(smc + O_QHI + off) = h;
            *(u32*)(smc + O_QLO + off) = l;
            split2(cs[i][j][2]*inv1, cs[i][j][3]*inv1, h, l);
            off = (u32)((r0 + 8)*QS + (8*j + cb)*2);
            *(u32*)(smc + O_QHI + off) = h;
            *(u32*)(smc + O_QLO + off) = l;
        }
    }
    __syncwarp();

    // ---- O = P V : per m-tile, accumulate; RED into L2-resident d_acc ----
    #pragma unroll
    for (int i = 0; i < 2; i++) {
        u32 ph[4][4], pll[4][4];
        #pragma unroll
        for (int s = 0; s < 4; s++) {
            u32 off = (u32)((wb + 16*i + lr + ((quad & 1) << 3)) * QS
                          + (16*s + ((quad & 2) << 2)) * 2);
            ldsm_x4(ph[s], qh + off);
            ldsm_x4(pll[s], ql + off);
        }
        int r0 = wb + 16*i + (lane >> 2);
        int ky = r0 >> 4;
        int kx0 = r0 & 15;
        int h = wy*8 - 8 + ky;
        int w0 = wx*8 - 8 + kx0;
        int w1 = w0 + 8;
        bool hok = (h >= 0 && h < HIMG);
        bool ok0 = hok && (w0 >= 0) && (w0 < WIMG);
        bool ok1 = hok && (w1 < WIMG);
        #pragma unroll
        for (int j = 0; j < 8; j++) {
            float o[4] = {0.f, 0.f, 0.f, 0.f};
            #pragma unroll
            for (int s = 0; s < 4; s++) {
                u32 off = (u32)((16*s + li) * QS + (8*j) * 2);
                u32 bh[2], bl[2];
                ldsm_x2t(bh, vh + off);
                ldsm_x2t(bl, vl + off);
                mma_bf16(o, ph[s], bh);
                mma_bf16(o, ph[s], bl);
                mma_bf16(o, pll[s], bh);
            }
            int d0 = 8*j + 2*(lane & 3);
            if (ok0) {
                float* dst = d_acc + ((size_t)b*NTOK + h*WIMG + w0)*64 + d0;
                asm volatile("red.global.add.v2.f32 [%0],{%1,%2};"
                             :: "l"(dst), "f"(o[0]), "f"(o[1]) : "memory");
            }
            if (ok1) {
                float* dst = d_acc + ((size_t)b*NTOK + h*WIMG + w1)*64 + d0;
                asm volatile("red.global.add.v2.f32 [%0],{%1,%2};"
                             :: "l"(dst), "f"(o[2]), "f"(o[3]) : "memory");
            }
        }
    }
}

// ---------------------------------------------------------------------------
// Kernel 4: out projection of the folded accumulator — 1 row/thread,
// 2 CTAs/SM (streaming, occupancy-first). d_acc is mostly L2-hot.
// ---------------------------------------------------------------------------
__global__ __launch_bounds__(256, 2) void proj_kernel(
    const float* __restrict__ pw, const float* __restrict__ pb,
    float* __restrict__ out)
{
    __shared__ float PW[4096];
    __shared__ float PB[64];
    int t = threadIdx.x;
    for (int i = t; i < 4096; i += 256) PW[i] = pw[i];
    if (t < 64) PB[t] = pb[t];
    __syncthreads();

    size_t r = (size_t)blockIdx.x * 256 + t;
    const ulonglong2* ar = (const ulonglong2*)(d_acc + r * 64);
    ulonglong2 a[16];
    #pragma unroll
    for (int i = 0; i < 16; i++) a[i] = ar[i];

    float* od = out + r * 64;
    #pragma unroll 4
    for (int d = 0; d < 64; d++) {
        const ulonglong2* wr = (const ulonglong2*)(PW + d*64);
        u64 s2 = 0ull;
        #pragma unroll
        for (int i = 0; i < 16; i++) {
            ulonglong2 w = wr[i];
            s2 = ffma2(a[i].x, w.x, s2);
            s2 = ffma2(a[i].y, w.y, s2);
        }
        od[d] = hsum2(s2) + PB[d];
    }
}

// ---------------------------------------------------------------------------
extern "C" void kernel_launch(void* const* d_in, const int* in_sizes, int n_in,
                              void* d_out, int out_size)
{
    const float* x       = (const float*)d_in[0];
    const float* pos_q   = (const float*)d_in[1];
    const float* pos_ksr = (const float*)d_in[2];
    const float* q_w     = (const float*)d_in[3];
    const float* kv_w    = (const float*)d_in[4];
    const float* sr_w    = (const float*)d_in[5];
    const float* sr_b    = (const float*)d_in[6];
    const float* ln_w    = (const float*)d_in[7];
    const float* ln_b    = (const float*)d_in[8];
    const float* proj_w  = (const float*)d_in[9];
    const float* proj_b  = (const float*)d_in[10];
    float* out = (float*)d_out;

    const int smem_conv = (16384 + 8192 + 192) * 4;
    cudaFuncSetAttribute(conv_ln_kv_kernel,
        cudaFuncAttributeMaxDynamicSharedMemorySize, smem_conv);
    cudaFuncSetAttribute(attn_kernel,
        cudaFuncAttributeMaxDynamicSharedMemorySize, SM_ATTN);

    zero_kernel<<<(BATCH*NTOK*CDIM/4)/256, 256>>>();
    qproj_kernel<<<(BATCH*NTOK)/256, 256>>>(x, q_w);
    conv_ln_kv_kernel<<<(BATCH*NS)/128, 128, smem_conv>>>(
        x, sr_w, sr_b, ln_w, ln_b, kv_w);
    attn_kernel<<<dim3(NWIN, BATCH), 256, SM_ATTN>>>(pos_q, pos_ksr);
    proj_kernel<<<(BATCH*NTOK)/256, 256>>>(proj_w, proj_b, out);
}

// round 14
// speedup vs baseline: 1.1108x; 1.0666x over previous
#include <cuda_runtime.h>
#include <cuda_bf16.h>
#include <cstdint>
#include <math.h>

// Problem constants
#define BATCH 2
#define HIMG 256
#define WIMG 256
#define NTOK (HIMG*WIMG)
#define CDIM 64
#define HS 128
#define WS 128
#define NS (HS*WS)
#define LH 33
#define LWIN 33
#define NWIN (LH*LWIN)
#define SCALE 0.125f
#define EPSLN 1e-5f

typedef unsigned long long u64;
typedef unsigned int u32;

// ---------------- packed f32x2 helpers (CUDA-core kernels) -----------------
__device__ __forceinline__ u64 pack2(float lo, float hi) {
    u64 r; asm("mov.b64 %0,{%1,%2};" : "=l"(r) : "f"(lo), "f"(hi)); return r;
}
__device__ __forceinline__ u64 ffma2(u64 a, u64 b, u64 c) {
    u64 d; asm("fma.rn.f32x2 %0,%1,%2,%3;" : "=l"(d) : "l"(a), "l"(b), "l"(c)); return d;
}
__device__ __forceinline__ float2 unpack2(u64 a) {
    float2 f; asm("mov.b64 {%0,%1},%2;" : "=f"(f.x), "=f"(f.y) : "l"(a)); return f;
}
__device__ __forceinline__ float hsum2(u64 a) { float2 f = unpack2(a); return f.x + f.y; }

// ---------------- mma.sync / ldmatrix helpers (sm_80+, in compute_100) -----
__device__ __forceinline__ uint32_t smem_u32(const void* p) {
    uint32_t a;
    asm("{ .reg .u64 tmp; cvta.to.shared.u64 tmp, %1; cvt.u32.u64 %0, tmp; }"
        : "=r"(a) : "l"(p));
    return a;
}
__device__ __forceinline__ void ldsm_x4(u32* r, u32 addr) {
    asm volatile("ldmatrix.sync.aligned.m8n8.x4.shared.b16 {%0,%1,%2,%3}, [%4];"
        : "=r"(r[0]), "=r"(r[1]), "=r"(r[2]), "=r"(r[3]) : "r"(addr));
}
__device__ __forceinline__ void ldsm_x2(u32* r, u32 addr) {
    asm volatile("ldmatrix.sync.aligned.m8n8.x2.shared.b16 {%0,%1}, [%2];"
        : "=r"(r[0]), "=r"(r[1]) : "r"(addr));
}
__device__ __forceinline__ void ldsm_x2t(u32* r, u32 addr) {
    asm volatile("ldmatrix.sync.aligned.m8n8.x2.trans.shared.b16 {%0,%1}, [%2];"
        : "=r"(r[0]), "=r"(r[1]) : "r"(addr));
}
__device__ __forceinline__ void mma_bf16(float* c, const u32* a, const u32* b) {
    asm volatile("mma.sync.aligned.m16n8k16.row.col.f32.bf16.bf16.f32 "
        "{%0,%1,%2,%3}, {%4,%5,%6,%7}, {%8,%9}, {%0,%1,%2,%3};"
        : "+f"(c[0]), "+f"(c[1]), "+f"(c[2]), "+f"(c[3])
        : "r"(a[0]), "r"(a[1]), "r"(a[2]), "r"(a[3]), "r"(b[0]), "r"(b[1]));
}

// pack (lo,hi) floats into bf16x2 (lo at [15:0])
__device__ __forceinline__ u32 bf2(float lo, float hi) {
    u32 r; asm("cvt.rn.satfinite.bf16x2.f32 %0, %1, %2;" : "=r"(r) : "f"(hi), "f"(lo));
    return r;
}
// split pair (f0,f1) -> hi bf16x2 and residual-lo bf16x2
__device__ __forceinline__ void split2(float f0, float f1, u32& h, u32& l) {
    h = bf2(f0, f1);
    float f0h = __uint_as_float(h << 16);
    float f1h = __uint_as_float(h & 0xFFFF0000u);
    l = bf2(f0 - f0h, f1 - f1h);
}

// Scratch — q + k + v + acc ≈ 84 MB fits in L2 (~126 MB)
__device__ float d_q  [BATCH*NTOK*CDIM];
__device__ float d_k  [BATCH*NS*CDIM];
__device__ float d_v  [BATCH*NS*CDIM];
__device__ float d_acc[BATCH*NTOK*CDIM];

// ---------------------------------------------------------------------------
// Kernel 0: zero the fold accumulator
// ---------------------------------------------------------------------------
__global__ __launch_bounds__(256) void zero_kernel()
{
    size_t i = (size_t)blockIdx.x * 256 + threadIdx.x;
    ((float4*)d_acc)[i] = make_float4(0.f, 0.f, 0.f, 0.f);
}

// ---------------------------------------------------------------------------
// Kernel 1: q = x @ q_w^T  — 2 rows/thread, f32x2 (R9 configuration)
// ---------------------------------------------------------------------------
__global__ __launch_bounds__(256) void qproj_kernel(
    const float* __restrict__ x, const float* __restrict__ qw)
{
    __shared__ float W[64*64];
    int t = threadIdx.x;
    for (int i = t; i < 4096; i += 256) W[i] = qw[i];
    __syncthreads();

    size_t r0 = (size_t)blockIdx.x * 512 + t;
    size_t r1 = r0 + 256;
    const ulonglong2* x0 = (const ulonglong2*)(x + r0 * 64);
    const ulonglong2* x1 = (const ulonglong2*)(x + r1 * 64);
    ulonglong2 a0[16], a1[16];
    #pragma unroll
    for (int i = 0; i < 16; i++) { a0[i] = x0[i]; a1[i] = x1[i]; }

    float* q0 = d_q + r0 * 64;
    float* q1 = d_q + r1 * 64;
    #pragma unroll 4
    for (int d = 0; d < 64; d++) {
        const ulonglong2* wr = (const ulonglong2*)(W + d*64);
        u64 s0 = 0ull, s1 = 0ull, s2 = 0ull, s3 = 0ull;
        #pragma unroll
        for (int i = 0; i < 16; i++) {
            ulonglong2 w = wr[i];
            s0 = ffma2(a0[i].x, w.x, s0);
            s1 = ffma2(a0[i].y, w.y, s1);
            s2 = ffma2(a1[i].x, w.x, s2);
            s3 = ffma2(a1[i].y, w.y, s3);
        }
        float2 f0 = unpack2(s0), g0 = unpack2(s1);
        float2 f1 = unpack2(s2), g1 = unpack2(s3);
        q0[d] = (f0.x + g0.x) + (f0.y + g0.y);
        q1[d] = (f1.x + g1.x) + (f1.y + g1.y);
    }
}

// ---------------------------------------------------------------------------
// Kernel 2: 2x2/s2 conv + bias -> LayerNorm -> k,v  (R9 configuration)
// ---------------------------------------------------------------------------
__global__ __launch_bounds__(256) void conv_ln_kv_kernel(
    const float* __restrict__ x,  const float* __restrict__ sr_w,
    const float* __restrict__ sr_b, const float* __restrict__ ln_w,
    const float* __restrict__ ln_b, const float* __restrict__ kv_w)
{
    extern __shared__ float sm[];
    float* Wc  = sm;
    float* KVW = sm + 16384;
    float* LNW = KVW + 8192;
    float* LNB = LNW + 64;
    float* SRB = LNB + 64;
    int t = threadIdx.x;

    for (int i = t; i < 16384; i += 256) {
        int c  = i >> 8;
        int ci = (i >> 2) & 63;
        int p  = i & 3;
        Wc[(p*64 + c)*64 + ci] = sr_w[i];
    }
    for (int i = t; i < 8192; i += 256) KVW[i] = kv_w[i];
    if (t < 64) { LNW[t] = ln_w[t]; LNB[t] = ln_b[t]; SRB[t] = sr_b[t]; }
    __syncthreads();

    int idx = blockIdx.x * 256 + t;
    int b  = idx >> 14;
    int hs = (idx >> 7) & 127;
    int ws = idx & 127;

    float acc[64];
    #pragma unroll
    for (int c = 0; c < 64; c++) acc[c] = SRB[c];

    for (int p = 0; p < 4; p++) {
        int h = hs*2 + (p >> 1), w = ws*2 + (p & 1);
        const ulonglong2* xin = (const ulonglong2*)(x + ((size_t)b*NTOK + h*WIMG + w)*64);
        ulonglong2 in[16];
        #pragma unroll
        for (int i = 0; i < 16; i++) in[i] = xin[i];
        #pragma unroll 4
        for (int c = 0; c < 64; c++) {
            const ulonglong2* wr = (const ulonglong2*)(Wc + (p*64 + c)*64);
            u64 s2 = 0ull;
            #pragma unroll
            for (int i = 0; i < 16; i++) {
                ulonglong2 w4 = wr[i];
                s2 = ffma2(in[i].x, w4.x, s2);
                s2 = ffma2(in[i].y, w4.y, s2);
            }
            acc[c] += hsum2(s2);
        }
    }

    float mu = 0.f, sq = 0.f;
    #pragma unroll
    for (int c = 0; c < 64; c++) { mu += acc[c]; sq += acc[c]*acc[c]; }
    mu *= (1.f/64.f);
    float var = sq * (1.f/64.f) - mu*mu;
    float rstd = rsqrtf(var + EPSLN);
    #pragma unroll
    for (int c = 0; c < 64; c++) acc[c] = (acc[c] - mu) * rstd * LNW[c] + LNB[c];

    u64 a2[32];
    #pragma unroll
    for (int i = 0; i < 32; i++) a2[i] = pack2(acc[2*i], acc[2*i+1]);

    float* kout = d_k + (size_t)idx * 64;
    float* vout = d_v + (size_t)idx * 64;
    #pragma unroll 4
    for (int d = 0; d < 64; d++) {
        const ulonglong2* wr = (const ulonglong2*)(KVW + d*64);
        u64 s2 = 0ull;
        #pragma unroll
        for (int i = 0; i < 16; i++) {
            ulonglong2 w4 = wr[i];
            s2 = ffma2(a2[2*i], w4.x, s2);
            s2 = ffma2(a2[2*i+1], w4.y, s2);
        }
        kout[d] = hsum2(s2);
    }
    #pragma unroll 4
    for (int d = 0; d < 64; d++) {
        const ulonglong2* wr = (const ulonglong2*)(KVW + (64+d)*64);
        u64 s2 = 0ull;
        #pragma unroll
        for (int i = 0; i < 16; i++) {
            ulonglong2 w4 = wr[i];
            s2 = ffma2(a2[2*i], w4.x, s2);
            s2 = ffma2(a2[2*i+1], w4.y, s2);
        }
        vout[d] = hsum2(s2);
    }
}

// ---------------------------------------------------------------------------
// Kernel 3: mma.sync attention (R9 structure) + lane-paired v4 REDs:
// lanes (2k,2k+1) in a quad cover contiguous 4-float spans; 4 shfl.down merge
// the pair and even lanes issue red.global.add.v4 — RED lane-ops halve.
// ---------------------------------------------------------------------------
#define QS 144
#define O_QHI 0
#define O_QLO 36864
#define O_KHI 73728
#define O_KLO 82944
#define O_VHI 92160
#define O_VLO 101376
#define SM_ATTN 110592

__global__ __launch_bounds__(256) void attn_kernel(
    const float* __restrict__ pos_q, const float* __restrict__ pos_k)
{
    extern __shared__ char smc[];
    uint32_t sb = smem_u32(smc);
    int t = threadIdx.x;
    int lane = t & 31;
    int wid  = t >> 5;          // 0..7
    int win = blockIdx.x, b = blockIdx.y;
    int wy = win / LWIN, wx = win % LWIN;

    // ---- stage roped K (hi/lo) and V (hi/lo, row-major [k][d]) ----
    {
        int r  = t >> 2;            // k-row 0..63
        int qt = t & 3;             // 16-channel quarter
        int kyy = r >> 3, kxx = r & 7;
        int hs = wy*4 - 4 + kyy, ws = wx*4 - 4 + kxx;
        bool ok = (hs >= 0 && hs < HS && ws >= 0 && ws < WS);
        size_t gro = ((size_t)b*NS + hs*WS + ws)*64 + qt*16;
        const float4* krow = (const float4*)(d_k + gro);
        const float4* vrow = (const float4*)(d_v + gro);
        const float4* prow = (const float4*)(pos_k + r*64 + qt*16);
        #pragma unroll
        for (int i = 0; i < 4; i++) {
            int c = qt*16 + i*4;
            float4 kk = ok ? krow[i] : make_float4(0.f,0.f,0.f,0.f);
            float4 p4 = prow[i];
            float e0 = p4.y*kk.y - p4.x*kk.x;
            float e1 = p4.y*kk.y + p4.x*kk.x;
            float e2 = p4.w*kk.w - p4.z*kk.z;
            float e3 = p4.w*kk.w + p4.z*kk.z;
            u32 h01, l01, h23, l23;
            split2(e0, e1, h01, l01);
            split2(e2, e3, h23, l23);
            u32 off = (u32)(r*QS + c*2);
            *(u64*)(smc + O_KHI + off) = ((u64)h23 << 32) | h01;
            *(u64*)(smc + O_KLO + off) = ((u64)l23 << 32) | l01;
            float4 vv = ok ? vrow[i] : make_float4(0.f,0.f,0.f,0.f);
            u32 vh01, vl01, vh23, vl23;
            split2(vv.x, vv.y, vh01, vl01);
            split2(vv.z, vv.w, vh23, vl23);
            *(u64*)(smc + O_VHI + off) = ((u64)vh23 << 32) | vh01;
            *(u64*)(smc + O_VLO + off) = ((u64)vl23 << 32) | vl01;
        }
    }

    // ---- stage roped+scaled Q row t (hi/lo) ----
    {
        int m = t;
        int ky = m >> 4, kx = m & 15;
        int h = wy*8 - 8 + ky, w = wx*8 - 8 + kx;
        bool valid = (h >= 0 && h < HIMG && w >= 0 && w < WIMG);
        const float4* qr = (const float4*)(d_q + ((size_t)b*NTOK + h*WIMG + w)*64);
        const float4* pr = (const float4*)(pos_q + m*64);
        #pragma unroll
        for (int i = 0; i < 16; i++) {
            float4 qq = valid ? qr[i] : make_float4(0.f,0.f,0.f,0.f);
            float4 p4 = pr[i];
            float e0 = (p4.y*qq.y - p4.x*qq.x) * SCALE;
            float e1 = (p4.y*qq.y + p4.x*qq.x) * SCALE;
            float e2 = (p4.w*qq.w - p4.z*qq.z) * SCALE;
            float e3 = (p4.w*qq.w + p4.z*qq.z) * SCALE;
            u32 h01, l01, h23, l23;
            split2(e0, e1, h01, l01);
            split2(e2, e3, h23, l23);
            u32 off = (u32)(m*QS + i*8);
            *(u64*)(smc + O_QHI + off) = ((u64)h23 << 32) | h01;
            *(u64*)(smc + O_QLO + off) = ((u64)l23 << 32) | l01;
        }
    }
    __syncthreads();

    int lr = lane & 7, quad = lane >> 3;
    int li = lane & 15;
    int wb = wid * 32;          // 32 q-rows per warp
    u32 qh = sb + O_QHI, ql = sb + O_QLO;
    u32 kh = sb + O_KHI, kl = sb + O_KLO;
    u32 vh = sb + O_VHI, vl = sb + O_VLO;

    // ---- S = Q K^T : C fragments cs[m-tile][n-tile][4] ----
    float cs[2][8][4];
    #pragma unroll
    for (int i = 0; i < 2; i++)
        #pragma unroll
        for (int j = 0; j < 8; j++)
            #pragma unroll
            for (int v = 0; v < 4; v++) cs[i][j][v] = 0.f;

    #pragma unroll
    for (int s = 0; s < 4; s++) {
        int d0 = 16*s;
        u32 ah[2][4], al[2][4];
        #pragma unroll
        for (int i = 0; i < 2; i++) {
            u32 off = (u32)((wb + 16*i + lr + ((quad & 1) << 3)) * QS
                          + (d0 + ((quad & 2) << 2)) * 2);
            ldsm_x4(ah[i], qh + off);
            ldsm_x4(al[i], ql + off);
        }
        #pragma unroll
        for (int j = 0; j < 8; j++) {
            u32 off = (u32)((8*j + (li & 7)) * QS + (d0 + ((li >> 3) << 3)) * 2);
            u32 bh[2], bl[2];
            ldsm_x2(bh, kh + off);
            ldsm_x2(bl, kl + off);
            #pragma unroll
            for (int i = 0; i < 2; i++) {
                mma_bf16(cs[i][j], ah[i], bh);
                mma_bf16(cs[i][j], ah[i], bl);
                mma_bf16(cs[i][j], al[i], bh);
            }
        }
    }

    // ---- softmax per row (quad shfl reduce), store P into Q smem ----
    #pragma unroll
    for (int i = 0; i < 2; i++) {
        float mx0 = -1e30f, mx1 = -1e30f;
        #pragma unroll
        for (int j = 0; j < 8; j++) {
            mx0 = fmaxf(mx0, fmaxf(cs[i][j][0], cs[i][j][1]));
            mx1 = fmaxf(mx1, fmaxf(cs[i][j][2], cs[i][j][3]));
        }
        mx0 = fmaxf(mx0, __shfl_xor_sync(0xffffffffu, mx0, 1));
        mx0 = fmaxf(mx0, __shfl_xor_sync(0xffffffffu, mx0, 2));
        mx1 = fmaxf(mx1, __shfl_xor_sync(0xffffffffu, mx1, 1));
        mx1 = fmaxf(mx1, __shfl_xor_sync(0xffffffffu, mx1, 2));
        float sm0 = 0.f, sm1 = 0.f;
        #pragma unroll
        for (int j = 0; j < 8; j++) {
            cs[i][j][0] = __expf(cs[i][j][0] - mx0);
            cs[i][j][1] = __expf(cs[i][j][1] - mx0);
            cs[i][j][2] = __expf(cs[i][j][2] - mx1);
            cs[i][j][3] = __expf(cs[i][j][3] - mx1);
            sm0 += cs[i][j][0] + cs[i][j][1];
            sm1 += cs[i][j][2] + cs[i][j][3];
        }
        sm0 += __shfl_xor_sync(0xffffffffu, sm0, 1);
        sm0 += __shfl_xor_sync(0xffffffffu, sm0, 2);
        sm1 += __shfl_xor_sync(0xffffffffu, sm1, 1);
        sm1 += __shfl_xor_sync(0xffffffffu, sm1, 2);
        float inv0 = 1.f / sm0, inv1 = 1.f / sm1;

        int r0 = wb + 16*i + (lane >> 2);
        int cb = 2*(lane & 3);
        #pragma unroll
        for (int j = 0; j < 8; j++) {
            u32 h, l;
            split2(cs[i][j][0]*inv0, cs[i][j][1]*inv0, h, l);
            u32 off = (u32)(r0*QS + (8*j + cb)*2);
            *(u32*)(smc + O_QHI + off) = h;
            *(u32*)(smc + O_QLO + off) = l;
            split2(cs[i][j][2]*inv1, cs[i][j][3]*inv1, h, l);
            off = (u32)((r0 + 8)*QS + (8*j + cb)*2);
            *(u32*)(smc + O_QHI + off) = h;
            *(u32*)(smc + O_QLO + off) = l;
        }
    }
    __syncwarp();

    // ---- O = P V : per m-tile; lane-paired v4 REDs into d_acc ----
    #pragma unroll
    for (int i = 0; i < 2; i++) {
        u32 ph[4][4], pll[4][4];
        #pragma unroll
        for (int s = 0; s < 4; s++) {
            u32 off = (u32)((wb + 16*i + lr + ((quad & 1) << 3)) * QS
                          + (16*s + ((quad & 2) << 2)) * 2);
            ldsm_x4(ph[s], qh + off);
            ldsm_x4(pll[s], ql + off);
        }
        int r0 = wb + 16*i + (lane >> 2);
        int ky = r0 >> 4;
        int kx0 = r0 & 15;
        int h = wy*8 - 8 + ky;
        int w0 = wx*8 - 8 + kx0;
        int w1 = w0 + 8;
        bool hok = (h >= 0 && h < HIMG);
        bool ok0 = hok && (w0 >= 0) && (w0 < WIMG);
        bool ok1 = hok && (w1 < WIMG);
        #pragma unroll
        for (int j = 0; j < 8; j++) {
            float o[4] = {0.f, 0.f, 0.f, 0.f};
            #pragma unroll
            for (int s = 0; s < 4; s++) {
                u32 off = (u32)((16*s + li) * QS + (8*j) * 2);
                u32 bh[2], bl[2];
                ldsm_x2t(bh, vh + off);
                ldsm_x2t(bl, vl + off);
                mma_bf16(o, ph[s], bh);
                mma_bf16(o, ph[s], bl);
                mma_bf16(o, pll[s], bh);
            }
            // pair lanes (2k, 2k+1): shfl peer's pair, even lane issues v4 RED
            float p0 = __shfl_down_sync(0xffffffffu, o[0], 1);
            float p1 = __shfl_down_sync(0xffffffffu, o[1], 1);
            float p2 = __shfl_down_sync(0xffffffffu, o[2], 1);
            float p3 = __shfl_down_sync(0xffffffffu, o[3], 1);
            if ((lane & 1) == 0) {
                int d0 = 8*j + 2*(lane & 3);   // lane&3 even -> d0 4-aligned
                if (ok0) {
                    float* dst = d_acc + ((size_t)b*NTOK + h*WIMG + w0)*64 + d0;
                    asm volatile("red.global.add.v4.f32 [%0],{%1,%2,%3,%4};"
                                 :: "l"(dst), "f"(o[0]), "f"(o[1]), "f"(p0), "f"(p1)
                                 : "memory");
                }
                if (ok1) {
                    float* dst = d_acc + ((size_t)b*NTOK + h*WIMG + w1)*64 + d0;
                    asm volatile("red.global.add.v4.f32 [%0],{%1,%2,%3,%4};"
                                 :: "l"(dst), "f"(o[2]), "f"(o[3]), "f"(p2), "f"(p3)
                                 : "memory");
                }
            }
        }
    }
}

// ---------------------------------------------------------------------------
// Kernel 4: out projection — 2 rows/thread (R9 configuration)
// ---------------------------------------------------------------------------
__global__ __launch_bounds__(256) void proj_kernel(
    const float* __restrict__ pw, const float* __restrict__ pb,
    float* __restrict__ out)
{
    __shared__ float PW[4096];
    __shared__ float PB[64];
    int t = threadIdx.x;
    for (int i = t; i < 4096; i += 256) PW[i] = pw[i];
    if (t < 64) PB[t] = pb[t];
    __syncthreads();

    size_t r0 = (size_t)blockIdx.x * 512 + t;
    size_t r1 = r0 + 256;
    const ulonglong2* x0 = (const ulonglong2*)(d_acc + r0 * 64);
    const ulonglong2* x1 = (const ulonglong2*)(d_acc + r1 * 64);
    ulonglong2 a0[16], a1[16];
    #pragma unroll
    for (int i = 0; i < 16; i++) { a0[i] = x0[i]; a1[i] = x1[i]; }

    float* o0 = out + r0 * 64;
    float* o1 = out + r1 * 64;
    #pragma unroll 4
    for (int d = 0; d < 64; d++) {
        const ulonglong2* wr = (const ulonglong2*)(PW + d*64);
        u64 s0 = 0ull, s1 = 0ull, s2 = 0ull, s3 = 0ull;
        #pragma unroll
        for (int i = 0; i < 16; i++) {
            ulonglong2 w = wr[i];
            s0 = ffma2(a0[i].x, w.x, s0);
            s1 = ffma2(a0[i].y, w.y, s1);
            s2 = ffma2(a1[i].x, w.x, s2);
            s3 = ffma2(a1[i].y, w.y, s3);
        }
        float2 f0 = unpack2(s0), g0 = unpack2(s1);
        float2 f1 = unpack2(s2), g1 = unpack2(s3);
        o0[d] = (f0.x + g0.x) + (f0.y + g0.y) + PB[d];
        o1[d] = (f1.x + g1.x) + (f1.y + g1.y) + PB[d];
    }
}

// ---------------------------------------------------------------------------
extern "C" void kernel_launch(void* const* d_in, const int* in_sizes, int n_in,
                              void* d_out, int out_size)
{
    const float* x       = (const float*)d_in[0];
    const float* pos_q   = (const float*)d_in[1];
    const float* pos_ksr = (const float*)d_in[2];
    const float* q_w     = (const float*)d_in[3];
    const float* kv_w    = (const float*)d_in[4];
    const float* sr_w    = (const float*)d_in[5];
    const float* sr_b    = (const float*)d_in[6];
    const float* ln_w    = (const float*)d_in[7];
    const float* ln_b    = (const float*)d_in[8];
    const float* proj_w  = (const float*)d_in[9];
    const float* proj_b  = (const float*)d_in[10];
    float* out = (float*)d_out;

    const int smem_conv = (16384 + 8192 + 192) * 4;
    cudaFuncSetAttribute(conv_ln_kv_kernel,
        cudaFuncAttributeMaxDynamicSharedMemorySize, smem_conv);
    cudaFuncSetAttribute(attn_kernel,
        cudaFuncAttributeMaxDynamicSharedMemorySize, SM_ATTN);

    zero_kernel<<<(BATCH*NTOK*CDIM/4)/256, 256>>>();
    qproj_kernel<<<(BATCH*NTOK)/512, 256>>>(x, q_w);
    conv_ln_kv_kernel<<<(BATCH*NS)/256, 256, smem_conv>>>(
        x, sr_w, sr_b, ln_w, ln_b, kv_w);
    attn_kernel<<<dim3(NWIN, BATCH), 256, SM_ATTN>>>(pos_q, pos_ksr);
    proj_kernel<<<(BATCH*NTOK)/512, 256>>>(proj_w, proj_b, out);
}